// round 12
// baseline (speedup 1.0000x reference)
#include <cuda_runtime.h>
#include <cstdint>

// Problem constants (fixed by setup_inputs: B=2, C=128, H=W=D=16)
#define NPOS 4096
#define CH   128
#define BATCH 2
#define KV_TILE 32
#define Q_TILE  128
#define NSPLIT  4
#define KV_PER  (NPOS / NSPLIT)   // 1024 keys per CTA

#define XS_PITCH 68
#define WS_PITCH 76
#define PROJ_SMEM_WORDS (32 * XS_PITCH + 160 * WS_PITCH)   // 14336 words = 57344 B

// Scratch (device globals: no allocation allowed)
__device__ __align__(16) unsigned g_Wb[160 * 64];                 // W bf16x2 [o][64w]
__device__ __align__(16) unsigned g_xb[BATCH * NPOS * 64];        // xT bf16x2 [b][n][64w]
__device__ __align__(16) unsigned g_Qb[BATCH * NPOS * 8];         // Q bf16x2, L2E-prescaled
__device__ __align__(16) unsigned g_Kb[BATCH * NPOS * 8];         // K bf16x2
__device__ __align__(16) unsigned g_Vt[BATCH * 128 * CH * 16];    // V^T bf16x2 [b][tile][c][16w]
__device__ float g_PO[NSPLIT * BATCH * CH * NPOS];                // O partials [sp][b][c][n]
__device__ float g_PL[NSPLIT * BATCH * NPOS];                     // l partials [sp][b][n]
__device__ unsigned g_cnt[BATCH * 32];                            // split-arrival counters

__device__ __forceinline__ unsigned packbf(float lo, float hi) {
    unsigned d;
    asm("cvt.rn.bf16x2.f32 %0, %1, %2;" : "=r"(d) : "f"(hi), "f"(lo));
    return d;
}
__device__ __forceinline__ void mma16(float* c, const unsigned* a, const unsigned* b) {
    asm volatile(
        "mma.sync.aligned.m16n8k16.row.col.f32.bf16.bf16.f32 "
        "{%0,%1,%2,%3}, {%4,%5,%6,%7}, {%8,%9}, {%0,%1,%2,%3};"
        : "+f"(c[0]), "+f"(c[1]), "+f"(c[2]), "+f"(c[3])
        : "r"(a[0]), "r"(a[1]), "r"(a[2]), "r"(a[3]), "r"(b[0]), "r"(b[1]));
}
__device__ __forceinline__ void ldmx4(unsigned* r, unsigned addr) {
    asm volatile("ldmatrix.sync.aligned.m8n8.x4.shared.b16 {%0,%1,%2,%3}, [%4];"
        : "=r"(r[0]), "=r"(r[1]), "=r"(r[2]), "=r"(r[3]) : "r"(addr));
}
__device__ __forceinline__ unsigned smem_u32(const void* p) {
    unsigned a;
    asm("{ .reg .u64 t; cvta.to.shared.u64 t, %1; cvt.u32.u64 %0, t; }" : "=r"(a) : "l"(p));
    return a;
}
__device__ __forceinline__ float ex2f(float x) {
    float y; asm("ex2.approx.f32 %0, %1;" : "=f"(y) : "f"(x)); return y;
}
__device__ __forceinline__ void cp16(unsigned dst, const void* src) {
    asm volatile(
        "{ .reg .u64 g; cvta.to.global.u64 g, %1; cp.async.cg.shared.global [%0], [g], 16; }"
        :: "r"(dst), "l"(src) : "memory");
}
__device__ __forceinline__ void cp_commit() {
    asm volatile("cp.async.commit_group;" ::: "memory");
}
__device__ __forceinline__ void cp_wait1() {
    asm volatile("cp.async.wait_group 1;" ::: "memory");
}
__device__ __forceinline__ void cp_wait0() {
    asm volatile("cp.async.wait_group 0;" ::: "memory");
}

// ---------------------------------------------------------------------------
// Prep kernel: (a) W fp32 -> bf16x2 g_Wb  (b) x fp32 -> transposed bf16x2
// g_xb[b][n][64w] via coalesced smem-tile transpose  (c) zero split counters.
// grid (128, 2), 256 threads: CTA = 32 voxels x all 128 channels.
// ---------------------------------------------------------------------------
__global__ __launch_bounds__(256) void prep_kernel(
    const float* __restrict__ x,
    const float* __restrict__ wq, const float* __restrict__ wk,
    const float* __restrict__ wv)
{
    __shared__ float xt[128][33];   // [c][n], pad 33

    const int b  = blockIdx.y;
    const int n0 = blockIdx.x * 32;
    const int t  = threadIdx.x;

    // (a) W convert: first 40 CTAs of b==0 (4 output rows each)
    if (b == 0 && blockIdx.x < 40) {
        const int o = blockIdx.x * 4 + (t >> 6);
        const int q = t & 63;
        const float* wrow = (o < 16) ? &wq[o * CH]
                          : (o < 32) ? &wk[(o - 16) * CH]
                                     : &wv[(o - 32) * CH];
        g_Wb[o * 64 + q] = packbf(wrow[2 * q], wrow[2 * q + 1]);
    }
    // (c) zero counters (graph replays must be deterministic)
    if (b == 1 && blockIdx.x < 32 && t == 0) {
        g_cnt[blockIdx.x] = 0;
        g_cnt[32 + blockIdx.x] = 0;
    }

    // (b) load x tile coalesced: 128 c x 32 n (1024 float4, 4/thread)
    #pragma unroll
    for (int i = 0; i < 4; i++) {
        const int idx = t + i * 256;
        const int c = idx >> 3, g4 = idx & 7;
        const float4 f = *(const float4*)&x[((size_t)b * CH + c) * NPOS + n0 + g4 * 4];
        xt[c][g4 * 4 + 0] = f.x;
        xt[c][g4 * 4 + 1] = f.y;
        xt[c][g4 * 4 + 2] = f.z;
        xt[c][g4 * 4 + 3] = f.w;
    }
    __syncthreads();

    // write transposed bf16x2: 32 n x 64 words (coalesced 256B per n-row)
    #pragma unroll
    for (int i = 0; i < 8; i++) {
        const int idx = t + i * 256;
        const int n = idx >> 6, wc = idx & 63;
        g_xb[((size_t)b * NPOS + n0 + n) * 64 + wc] = packbf(xt[2 * wc][n], xt[2 * wc + 1][n]);
    }
}

// ---------------------------------------------------------------------------
// Tensor-core projection: staging is now 12 cp.async 16B chunks / thread
// (W 10 + x 2) from pre-converted bf16x2 globals -> no serial LDG/cvt chain.
// One barrier, 8 k16 steps, epilogue emits attention-ready layouts.
// Dynamic smem 57344 B: xs[32][68] (conflict-free ldmatrix), ws[160][76]
// (B-frag banks (12*lr+lc)%32 distinct).
// ---------------------------------------------------------------------------
__global__ __launch_bounds__(256) void proj_kernel(
    const float* __restrict__ bq, const float* __restrict__ bk,
    const float* __restrict__ bv)
{
    extern __shared__ unsigned smem[];
    unsigned* xs = smem;                     // [32][XS_PITCH]
    unsigned* ws = smem + 32 * XS_PITCH;     // [160][WS_PITCH]

    const int b    = blockIdx.y;
    const int n0g  = blockIdx.x * 32;
    const int t    = threadIdx.x;
    const int lane = t & 31;
    const int w    = t >> 5;
    const int wm   = w & 1;        // 16-voxel half
    const int wn   = w >> 1;       // 40-output quarter (5 n8 tiles)
    const int lr   = lane >> 2;
    const int lc   = lane & 3;
    const size_t bofs = (size_t)b * NPOS;

    const unsigned xs_a = smem_u32(xs);
    const unsigned ws_a = smem_u32(ws);

    // ---- stage W: 2560 16B chunks via cp.async ----
    #pragma unroll
    for (int i = 0; i < 10; i++) {
        const int ch = t + i * 256;
        const int o = ch >> 4, q4 = ch & 15;
        cp16(ws_a + (o * WS_PITCH + q4 * 4) * 4, g_Wb + o * 64 + q4 * 4);
    }
    // ---- stage xT: 512 16B chunks via cp.async ----
    #pragma unroll
    for (int i = 0; i < 2; i++) {
        const int ch = t + i * 256;
        const int n = ch >> 4, q4 = ch & 15;
        cp16(xs_a + (n * XS_PITCH + q4 * 4) * 4,
             g_xb + (bofs + n0g + n) * 64 + q4 * 4);
    }
    cp_commit();

    // accumulators initialized with bias (overlaps the async copies)
    float acc[5][4];
    #pragma unroll
    for (int nt = 0; nt < 5; nt++) {
        const int o0 = wn * 40 + nt * 8 + 2 * lc;
        float blo, bhi;
        if (o0 < 16)       { blo = bq[o0];      bhi = bq[o0 + 1]; }
        else if (o0 < 32)  { blo = bk[o0 - 16]; bhi = bk[o0 - 15]; }
        else               { blo = bv[o0 - 32]; bhi = bv[o0 - 31]; }
        acc[nt][0] = blo; acc[nt][1] = bhi; acc[nt][2] = blo; acc[nt][3] = bhi;
    }

    const int arow  = wm * 16 + (lane & 7) + ((lane >> 3) & 1) * 8;
    const int awofs = (lane >> 4) * 4;
    const unsigned xs_base = xs_a + (arow * XS_PITCH + awofs) * 4;

    cp_wait0();
    __syncthreads();   // the ONLY barrier

    // ---- 8 k16 steps over 128 channels ----
    #pragma unroll
    for (int s = 0; s < 8; s++) {
        unsigned a[4];
        ldmx4(a, xs_base + s * 32);
        #pragma unroll
        for (int nt = 0; nt < 5; nt++) {
            const int o = wn * 40 + nt * 8 + lr;
            unsigned bb[2];
            bb[0] = ws[o * WS_PITCH + s * 8 + lc];
            bb[1] = ws[o * WS_PITCH + s * 8 + lc + 4];
            mma16(acc[nt], a, bb);
        }
    }

    // ---- epilogue: bf16x2 attention-ready layouts ----
    const float L2E = 1.4426950408889634f;
    const int n0  = n0g + wm * 16 + lr;
    const int n1  = n0 + 8;
    const int ktg = n0g >> 5;
    const bool lrodd = (lr & 1);

    #pragma unroll
    for (int nt = 0; nt < 5; nt++) {
        const int o0 = wn * 40 + nt * 8 + 2 * lc;
        if (o0 < 16) {
            g_Qb[(bofs + n0) * 8 + (o0 >> 1)] = packbf(L2E * acc[nt][0], L2E * acc[nt][1]);
            g_Qb[(bofs + n1) * 8 + (o0 >> 1)] = packbf(L2E * acc[nt][2], L2E * acc[nt][3]);
        } else if (o0 < 32) {
            g_Kb[(bofs + n0) * 8 + ((o0 - 16) >> 1)] = packbf(acc[nt][0], acc[nt][1]);
            g_Kb[(bofs + n1) * 8 + ((o0 - 16) >> 1)] = packbf(acc[nt][2], acc[nt][3]);
        } else {
            const int c = o0 - 32;
            const float sh0 = __shfl_xor_sync(0xffffffffu, acc[nt][0], 4);
            const float sh1 = __shfl_xor_sync(0xffffffffu, acc[nt][1], 4);
            const float sh2 = __shfl_xor_sync(0xffffffffu, acc[nt][2], 4);
            const float sh3 = __shfl_xor_sync(0xffffffffu, acc[nt][3], 4);
            unsigned* vrow0 = &g_Vt[(((size_t)b * 128 + ktg) * CH + c) * 16];
            unsigned* vrow1 = vrow0 + 16;
            if (!lrodd) {
                const int jp = (wm * 16 + lr) >> 1;
                vrow0[jp] = packbf(acc[nt][0], sh0);
                vrow1[jp] = packbf(acc[nt][1], sh1);
            } else {
                const int jp = (wm * 16 + lr + 7) >> 1;
                vrow0[jp] = packbf(sh2, acc[nt][2]);
                vrow1[jp] = packbf(sh3, acc[nt][3]);
            }
        }
    }
}

// ---------------------------------------------------------------------------
// bf16 m16n8k16 flash attention, Q_TILE=128, split-KV x4. Hot loop unchanged
// (cp.async 3-stage ring, ldmatrix B-frags). NEW: split-K semaphore — the
// last-arriving split CTA for each (b, q-tile) performs the final combine
// (gamma * sum(O)/sum(l) + x) in its epilogue; no separate combine kernel.
// ---------------------------------------------------------------------------
__global__ __launch_bounds__(256) void attn_kernel(
    const float* __restrict__ x, const float* __restrict__ gamma,
    float* __restrict__ out)
{
    __shared__ __align__(16) unsigned ksw[3][KV_TILE][12];  // K bf16x2 words
    __shared__ __align__(16) unsigned vsw[3][CH][20];       // V^T bf16x2 words
    __shared__ unsigned s_last;

    const int b    = blockIdx.y & 1;
    const int sp   = blockIdx.y >> 1;
    const int q0   = blockIdx.x * Q_TILE;
    const int t    = threadIdx.x;
    const int w    = t >> 5;
    const int lane = t & 31;
    const int lr   = lane >> 2;
    const int lc   = lane & 3;
    const size_t bofs = (size_t)b * NPOS;
    const int kvbase = sp * KV_PER;

    // Q A-fragment: already bf16 + log2(e) prescaled
    unsigned qa[4];
    {
        const unsigned* qb = &g_Qb[(bofs + q0 + w * 16) * 8];
        qa[0] = qb[(lr    ) * 8 + lc    ];
        qa[1] = qb[(lr + 8) * 8 + lc    ];
        qa[2] = qb[(lr    ) * 8 + lc + 4];
        qa[3] = qb[(lr + 8) * 8 + lc + 4];
    }

    float oc[16][4];
    #pragma unroll
    for (int nt = 0; nt < 16; nt++)
        #pragma unroll
        for (int r = 0; r < 4; r++) oc[nt][r] = 0.f;
    float lsum0 = 0.f, lsum1 = 0.f;

    const int vc = t >> 2;
    const int vq = (t & 3) * 4;
    const int kr = t >> 1;
    const int kq = (t & 1) * 4;

    const unsigned* vsrc = &g_Vt[((size_t)b * 128 + (kvbase >> 5)) * CH * 16];
    const unsigned* ksrc = &g_Kb[(bofs + kvbase) * 8];

    const unsigned VBUF = CH * 20 * 4;
    const unsigned KBUF = KV_TILE * 12 * 4;
    const unsigned vdst0 = smem_u32(vsw) + (vc * 20 + vq) * 4;
    const unsigned vdst1 = vdst0 + 64 * 20 * 4;
    const unsigned kdst  = smem_u32(ksw) + (kr * 12 + kq) * 4;

    const int lm = lane >> 3;
    const int lrr = lane & 7;
    const unsigned koff = (unsigned)((((lm >> 1) * 8 + lrr) * 12 + (lm & 1) * 4) * 4);
    const unsigned voff = (unsigned)((((lm >> 1) * 8 + lrr) * 20 + (lm & 1) * 4) * 4);
    const unsigned kbase0 = smem_u32(ksw) + koff;
    const unsigned vbase0 = smem_u32(vsw) + voff;

    #define ISSUE(tt, buf) do {                                              \
        const unsigned* vs = vsrc + (((size_t)(tt) * CH + vc) * 16 + vq);    \
        cp16(vdst0 + (unsigned)(buf) * VBUF, vs);                            \
        cp16(vdst1 + (unsigned)(buf) * VBUF, vs + 64 * 16);                  \
        if (t < 64)                                                          \
            cp16(kdst + (unsigned)(buf) * KBUF,                              \
                 ksrc + (((tt) * KV_TILE + kr) * 8 + kq));                   \
        cp_commit();                                                         \
    } while (0)

    ISSUE(0, 0);
    ISSUE(1, 1);

    const int NT = KV_PER / KV_TILE;   // 32
    for (int kt = 0; kt < NT; kt++) {
        const int buf = kt % 3;
        cp_wait1();
        __syncthreads();

        if (kt + 2 < NT) {
            ISSUE(kt + 2, (kt + 2) % 3);
        } else {
            cp_commit();
        }

        const unsigned kbb = kbase0 + (unsigned)buf * KBUF;
        const unsigned vbb = vbase0 + (unsigned)buf * VBUF;

        #pragma unroll
        for (int s = 0; s < 2; s++) {
            unsigned kb[4];
            ldmx4(kb, kbb + (unsigned)s * (16 * 48));

            unsigned pa[4];
            #pragma unroll
            for (int h = 0; h < 2; h++) {
                float sc[4] = {0.f, 0.f, 0.f, 0.f};
                mma16(sc, qa, &kb[2 * h]);
                const float p0 = ex2f(sc[0]);
                const float p1 = ex2f(sc[1]);
                const float p2 = ex2f(sc[2]);
                const float p3 = ex2f(sc[3]);
                lsum0 += p0 + p1;
                lsum1 += p2 + p3;
                pa[2 * h    ] = packbf(p0, p1);
                pa[2 * h + 1] = packbf(p2, p3);
            }

            #pragma unroll
            for (int p = 0; p < 8; p++) {
                unsigned vb[4];
                ldmx4(vb, vbb + (unsigned)p * (16 * 80) + (unsigned)s * 32);
                mma16(oc[2 * p    ], pa, &vb[0]);
                mma16(oc[2 * p + 1], pa, &vb[2]);
            }
        }
    }

    lsum0 += __shfl_xor_sync(0xffffffffu, lsum0, 1);
    lsum0 += __shfl_xor_sync(0xffffffffu, lsum0, 2);
    lsum1 += __shfl_xor_sync(0xffffffffu, lsum1, 1);
    lsum1 += __shfl_xor_sync(0xffffffffu, lsum1, 2);

    // ---- write this split's partials ----
    float* po = &g_PO[(size_t)(sp * BATCH + b) * CH * NPOS];
    const int r0 = w * 16 + lr;
    const int r1 = r0 + 8;
    #pragma unroll
    for (int nt2 = 0; nt2 < 16; nt2++) {
        const int c = nt2 * 8 + 2 * lc;
        po[(size_t)(c    ) * NPOS + q0 + r0] = oc[nt2][0];
        po[(size_t)(c + 1) * NPOS + q0 + r0] = oc[nt2][1];
        po[(size_t)(c    ) * NPOS + q0 + r1] = oc[nt2][2];
        po[(size_t)(c + 1) * NPOS + q0 + r1] = oc[nt2][3];
    }
    if (lc == 0) {
        g_PL[(size_t)(sp * BATCH + b) * NPOS + q0 + r0] = lsum0;
        g_PL[(size_t)(sp * BATCH + b) * NPOS + q0 + r1] = lsum1;
    }

    // ---- split-K semaphore: last split combines (threadFenceReduction pattern) ----
    __threadfence();
    __syncthreads();
    if (t == 0) {
        const unsigned old = atomicAdd(&g_cnt[b * 32 + blockIdx.x], 1u);
        s_last = (old == NSPLIT - 1) ? 1u : 0u;
    }
    __syncthreads();

    if (s_last) {
        __threadfence();
        const float gm = gamma[0];
        const float4* PO4 = (const float4*)g_PO;
        const float4* PL4 = (const float4*)g_PL;
        const float4* X4  = (const float4*)x;
        float4* OUT4 = (float4*)out;
        const int q4base = blockIdx.x * 32;
        const size_t SP4 = (size_t)BATCH * CH * NPOS / 4;   // 262144
        const size_t SL4 = (size_t)BATCH * NPOS / 4;        // 2048

        for (int i = t; i < CH * 32; i += 256) {
            const int c = i >> 5, n4 = i & 31;
            const size_t po4 = (size_t)(b * CH + c) * (NPOS / 4) + q4base + n4;
            const size_t pl4 = (size_t)b * (NPOS / 4) + q4base + n4;
            const float4 o0 = PO4[po4];
            const float4 o1 = PO4[SP4 + po4];
            const float4 o2 = PO4[2 * SP4 + po4];
            const float4 o3 = PO4[3 * SP4 + po4];
            const float4 l0 = PL4[pl4];
            const float4 l1 = PL4[SL4 + pl4];
            const float4 l2 = PL4[2 * SL4 + pl4];
            const float4 l3 = PL4[3 * SL4 + pl4];
            const float4 xv = X4[po4];
            float4 r;
            r.x = gm * (o0.x + o1.x + o2.x + o3.x) / (l0.x + l1.x + l2.x + l3.x) + xv.x;
            r.y = gm * (o0.y + o1.y + o2.y + o3.y) / (l0.y + l1.y + l2.y + l3.y) + xv.y;
            r.z = gm * (o0.z + o1.z + o2.z + o3.z) / (l0.z + l1.z + l2.z + l3.z) + xv.z;
            r.w = gm * (o0.w + o1.w + o2.w + o3.w) / (l0.w + l1.w + l2.w + l3.w) + xv.w;
            OUT4[po4] = r;
        }
    }
    #undef ISSUE
}

extern "C" void kernel_launch(void* const* d_in, const int* in_sizes, int n_in,
                              void* d_out, int out_size)
{
    const float* x     = (const float*)d_in[0];
    const float* wq    = (const float*)d_in[1];
    const float* bq    = (const float*)d_in[2];
    const float* wk    = (const float*)d_in[3];
    const float* bk    = (const float*)d_in[4];
    const float* wv    = (const float*)d_in[5];
    const float* bv    = (const float*)d_in[6];
    const float* gamma = (const float*)d_in[7];
    float* out = (float*)d_out;

    const int proj_smem = PROJ_SMEM_WORDS * 4;   // 57344 B
    cudaFuncSetAttribute(proj_kernel, cudaFuncAttributeMaxDynamicSharedMemorySize, proj_smem);

    dim3 gridPre(NPOS / 32, BATCH);              // 128 x 2
    prep_kernel<<<gridPre, 256>>>(x, wq, wk, wv);

    dim3 gridP(NPOS / 32, BATCH);                // 128 x 2 = 256 CTAs
    proj_kernel<<<gridP, 256, proj_smem>>>(bq, bk, bv);

    dim3 gridA(NPOS / Q_TILE, BATCH * NSPLIT);   // 32 x 8 = 256 CTAs
    attn_kernel<<<gridA, 256>>>(x, gamma, out);
}